// round 12
// baseline (speedup 1.0000x reference)
#include <cuda_runtime.h>
#include <math.h>
#include <stdint.h>

// SparseMoEGate via mma.sync (HMMA) fp16x2 exact-split GEMM (3 MMAs/k-step).
// R12 = R10 pipeline with 1024-thread CTAs: 32 warps (8/SMSP), each warp
// 16 tokens x 16 experts (2 n-tiles, 6 MMAs/kstep). Latency hiding 2x.
// x[16384,4096] f32, w[64,4096] f32
// out: [topk_idx as f32 (2T)] [topk_weight (2T)] [aux_loss (1)]

#define T_TOKENS 16384
#define C_DIM    4096
#define E_EXP    64
#define ALPHA    0.01f
#define WSCALE   16384.0f
#define WDESC    6.103515625e-05f   // 2^-14

#define BT    128             // tokens per CTA
#define NTH   1024            // 32 warps
#define NKS   (C_DIM / 16)    // 256 k-steps
#define KPS   4               // k-steps per stage
#define NST   (NKS / KPS)     // 64 stages

#define XROW  272             // bytes per x row in smem (256B data + 16B pad)
#define XOFF_W 34816          // 128 * 272
#define WSTG  16384           // w bytes per stage (4 ksteps x 4KB)
#define SLOT  (XOFF_W + WSTG) // 51200
#define SMEM_BYTES (3 * SLOT) // 153600

__device__ float g_ssum[E_EXP];
__device__ float g_cnt[E_EXP];
__device__ unsigned g_done;
// B tiles, ldmatrix layout: [ks][nt][pl][t][n-row] 16B rows  (1 MB)
__device__ __align__(16) uint32_t w_frag[NKS * 1024];

// exact 2-way fp16 split of (even,odd) f32 pair -> 2 packed f16x2 (lo=even)
__device__ __forceinline__ void split2v(float fe, float fo,
                                        uint32_t& h1, uint32_t& h2) {
    asm("cvt.rn.f16x2.f32 %0, %1, %2;" : "=r"(h1) : "f"(fo), "f"(fe));
    float ge, go;
    asm("{ .reg .f16 l, h; mov.b32 {l, h}, %2;"
        " cvt.f32.f16 %0, l; cvt.f32.f16 %1, h; }"
        : "=f"(ge), "=f"(go) : "r"(h1));
    asm("cvt.rn.f16x2.f32 %0, %1, %2;" : "=r"(h2) : "f"(fo - go), "f"(fe - ge));
}

#define MMA(acc, A, B)                                                        \
    asm volatile(                                                             \
        "mma.sync.aligned.m16n8k16.row.col.f32.f16.f16.f32 "                  \
        "{%0,%1,%2,%3}, {%4,%5,%6,%7}, {%8,%9}, {%0,%1,%2,%3};"               \
        : "+f"(acc[0]), "+f"(acc[1]), "+f"(acc[2]), "+f"(acc[3])              \
        : "r"(A[0]), "r"(A[1]), "r"(A[2]), "r"(A[3]), "r"(B.x), "r"(B.y))

#define LDMX4(r0, r1, r2, r3, a)                                              \
    asm volatile("ldmatrix.sync.aligned.m8n8.x4.shared.b16 {%0,%1,%2,%3}, [%4];" \
        : "=r"(r0), "=r"(r1), "=r"(r2), "=r"(r3) : "r"(a))

__device__ __forceinline__ void cp16(uint32_t sa, const void* g) {
    asm volatile("cp.async.cg.shared.global [%0], [%1], 16;" :: "r"(sa), "l"(g));
}
__device__ __forceinline__ uint32_t smem_u32(const void* p) {
    uint32_t a;
    asm("{ .reg .u64 t; cvta.to.shared.u64 t, %1; cvt.u32.u64 %0, t; }"
        : "=r"(a) : "l"(p));
    return a;
}

// Precompute w fp16x2 planes (scaled by 2^14) in ldmatrix tile layout.
__global__ void prep_w(const float* __restrict__ w) {
    if (blockIdx.x == 0) {
        if (threadIdx.x < E_EXP) {
            g_ssum[threadIdx.x] = 0.f;
            g_cnt[threadIdx.x] = 0.f;
        }
        if (threadIdx.x == 64) g_done = 0;
    }
    int i = blockIdx.x * blockDim.x + threadIdx.x;   // 32768 threads
    int t = i & 1, e = (i >> 1) & 63, ks = i >> 7;
    const float* src = w + (size_t)e * C_DIM + ks * 16 + t * 8;
    uint32_t h1[4], h2[4];
    #pragma unroll
    for (int p = 0; p < 4; p++)
        split2v(src[2 * p] * WSCALE, src[2 * p + 1] * WSCALE, h1[p], h2[p]);
    int nt = e >> 3, n = e & 7;
    char* base = (char*)w_frag + (size_t)ks * 4096 + nt * 512 + t * 128 + n * 16;
    *(uint4*)(base)       = make_uint4(h1[0], h1[1], h1[2], h1[3]);  // plane 1
    *(uint4*)(base + 256) = make_uint4(h2[0], h2[1], h2[2], h2[3]);  // plane 2
}

extern __shared__ __align__(16) char dsm[];

__global__ __launch_bounds__(NTH, 1) void gate_kernel(
    const float* __restrict__ x, float* __restrict__ out)
{
    __shared__ int s_cnt[E_EXP];
    __shared__ int s_last;
    float* lg = (float*)dsm;                 // epilogue overlay [BT][65]

    const int tid = threadIdx.x, blk = blockIdx.x;
    const int wid = tid >> 5, lane = tid & 31;
    const int tg = wid & 7;                  // token group (16 tokens)
    const int nq = wid >> 3;                 // expert quarter (16 experts)
    const int qr = lane >> 2, qc = lane & 3;
    const uint32_t sb = smem_u32(dsm);

    const int xr_lo = tg * 16 + qr;
    const int xr_hi = xr_lo + 8;
    // ldmatrix base for this warp's 2 n-tiles
    const uint32_t wlane = (nq * 2) * 512 + ((lane >> 3) * 128) + ((lane & 7) * 16);

    // cp geometry: 1024 thr -> 128 rows x 8 segs(16B) in one pass
    const int crow = tid >> 3, cseg = tid & 7;
    const float* xg = x + (size_t)(blk * BT + crow) * C_DIM + cseg * 4;

    if (tid < E_EXP) s_cnt[tid] = 0;

    float acc[2][4];
    #pragma unroll
    for (int j = 0; j < 2; j++)
        #pragma unroll
        for (int q = 0; q < 4; q++) acc[j][q] = 0.f;

    auto stage_cp = [&](int st, int slot) {
        const uint32_t base = sb + slot * SLOT;
        // x: 128 rows x 256B (272B pitch), fully coalesced
        #pragma unroll
        for (int kh = 0; kh < 2; kh++)
            cp16(base + crow * XROW + kh * 128 + cseg * 16,
                 xg + st * 64 + kh * 32);
        // w tiles: 16KB in one shot (1024 x 16B)
        cp16(base + XOFF_W + tid * 16,
             (const char*)w_frag + (size_t)st * WSTG + tid * 16);
    };

    stage_cp(0, 0); asm volatile("cp.async.commit_group;");
    stage_cp(1, 1); asm volatile("cp.async.commit_group;");

    #pragma unroll 1
    for (int i = 0; i < NST; i++) {
        asm volatile("cp.async.wait_group 1;");
        __syncthreads();                     // stage i visible; slot (i+2)%3 free

        if (i + 2 < NST) stage_cp(i + 2, (i + 2) % 3);
        asm volatile("cp.async.commit_group;");

        const char* xs = dsm + (i % 3) * SLOT;
        const uint32_t wbase = sb + (i % 3) * SLOT + XOFF_W + wlane;

        #pragma unroll
        for (int kk = 0; kk < KPS; kk++) {
            float2 x0 = *(const float2*)(xs + xr_lo * XROW + kk * 64 + qc * 8);
            float2 x1 = *(const float2*)(xs + xr_hi * XROW + kk * 64 + qc * 8);
            float2 x2 = *(const float2*)(xs + xr_lo * XROW + kk * 64 + 32 + qc * 8);
            float2 x3 = *(const float2*)(xs + xr_hi * XROW + kk * 64 + 32 + qc * 8);

            // A frag order [r0/klo, r1/klo, r0/khi, r1/khi]
            uint32_t a1[4], a2[4];
            split2v(x0.x, x0.y, a1[0], a2[0]);
            split2v(x1.x, x1.y, a1[1], a2[1]);
            split2v(x2.x, x2.y, a1[2], a2[2]);
            split2v(x3.x, x3.y, a1[3], a2[3]);

            uint2 b1[2], b2[2];
            #pragma unroll
            for (int j = 0; j < 2; j++) {
                uint32_t r0, r1, r2, r3;
                LDMX4(r0, r1, r2, r3, wbase + kk * 4096 + j * 512);
                b1[j].x = r0; b1[j].y = r1;
                b2[j].x = r2; b2[j].y = r3;
            }
            #pragma unroll
            for (int j = 0; j < 2; j++) MMA(acc[j], a1, b1[j]);
            #pragma unroll
            for (int j = 0; j < 2; j++) MMA(acc[j], a2, b1[j]);
            #pragma unroll
            for (int j = 0; j < 2; j++) MMA(acc[j], a1, b2[j]);
        }
    }
    __syncthreads();    // staging done; reuse dsm as logits

    // scatter logits (descaled): row = tg*16 + qr (+8), col = (nq*2+j)*8 + 2*qc
    const int lr0 = tg * 16 + qr;
    #pragma unroll
    for (int j = 0; j < 2; j++) {
        const int e = (nq * 2 + j) * 8 + 2 * qc;
        lg[lr0 * 65 + e]           = acc[j][0] * WDESC;
        lg[lr0 * 65 + e + 1]       = acc[j][1] * WDESC;
        lg[(lr0 + 8) * 65 + e]     = acc[j][2] * WDESC;
        lg[(lr0 + 8) * 65 + e + 1] = acc[j][3] * WDESC;
    }
    __syncthreads();

    if (tid < BT) {
        float* row = lg + tid * 65;
        float v1 = -1e30f, v2 = -1e30f;
        int i1 = 0, i2 = 0;
        #pragma unroll
        for (int e = 0; e < E_EXP; e++) {
            float v = row[e];
            if (v > v1)      { v2 = v1; i2 = i1; v1 = v; i1 = e; }
            else if (v > v2) { v2 = v;  i2 = e; }
        }
        float Z = 0.f;
        #pragma unroll
        for (int e = 0; e < E_EXP; e++) {
            float ex = expf(row[e] - v1);
            row[e] = ex; Z += ex;
        }
        float rz = 1.0f / Z;
        #pragma unroll
        for (int e = 0; e < E_EXP; e++) row[e] *= rz;
        float s1 = row[i1], s2 = row[i2];
        float inv = 1.0f / (s1 + s2);
        int gt = blk * BT + tid;
        out[2 * gt]     = (float)i1;
        out[2 * gt + 1] = (float)i2;
        out[2 * T_TOKENS + 2 * gt]     = s1 * inv;
        out[2 * T_TOKENS + 2 * gt + 1] = s2 * inv;
        atomicAdd(&s_cnt[i1], 1);
        atomicAdd(&s_cnt[i2], 1);
    }
    __syncthreads();

    if (tid < E_EXP) {
        float sum = 0.f;
        for (int t = 0; t < BT; t++) sum += lg[t * 65 + tid];
        atomicAdd(&g_ssum[tid], sum);
        atomicAdd(&g_cnt[tid], (float)s_cnt[tid]);
    }
    __syncthreads();

    // last CTA computes aux loss
    if (tid == 0) {
        __threadfence();
        s_last = (atomicAdd(&g_done, 1u) == gridDim.x - 1);
    }
    __syncthreads();
    if (s_last) {
        if (tid < E_EXP) lg[tid] = g_ssum[tid] * g_cnt[tid];
        __syncthreads();
        if (tid == 0) {
            float s = 0.f;
            for (int e = 0; e < E_EXP; e++) s += lg[e];
            out[4 * T_TOKENS] = s * (ALPHA * (float)E_EXP /
                ((float)T_TOKENS * 2.0f * (float)T_TOKENS));
        }
    }
}

extern "C" void kernel_launch(void* const* d_in, const int* in_sizes, int n_in,
                              void* d_out, int out_size) {
    const float* x = (const float*)d_in[0];
    const float* w = (const float*)d_in[1];
    float* out = (float*)d_out;
    cudaFuncSetAttribute(gate_kernel,
                         cudaFuncAttributeMaxDynamicSharedMemorySize, SMEM_BYTES);
    prep_w<<<128, 256>>>(w);
    gate_kernel<<<T_TOKENS / BT, NTH, SMEM_BYTES>>>(x, out);
}

// round 15
// speedup vs baseline: 1.0566x; 1.0566x over previous
#include <cuda_runtime.h>
#include <math.h>
#include <stdint.h>

// SparseMoEGate via mma.sync (HMMA) fp16x2 exact-split GEMM (3 MMAs/k-step).
// R15 = R14 with the cp.async visibility race fixed: __syncthreads hoisted to
// right after cp.async.wait_group (R10 ordering). x split hoisted out of hot
// loop; compute = pure ldmatrix(A,B) + MMA. 16 warps, 1 barrier/stage.
// x[16384,4096] f32, w[64,4096] f32
// out: [topk_idx as f32 (2T)] [topk_weight (2T)] [aux_loss (1)]

#define T_TOKENS 16384
#define C_DIM    4096
#define E_EXP    64
#define ALPHA    0.01f
#define WSCALE   16384.0f
#define WDESC    6.103515625e-05f   // 2^-14

#define BT    128             // tokens per CTA
#define NTH   512             // 16 warps
#define NKS   (C_DIM / 16)    // 256 k-steps
#define KPS   4               // k-steps per stage
#define NST   (NKS / KPS)     // 64 stages

// A-plane buffer: per (tg, kstep): 2 planes x 4 tiles x 128B = 1024B,
// padded kstep stride 1056B (conflict-free STS.128), tg stride 4224B.
#define KK_STR 1056
#define TG_STR 4224           // 4 * KK_STR
#define P_STG  33792          // 8 * TG_STR  (one stage of planes)
#define W_OFF  67584          // 2 * P_STG
#define WSTG   16384          // w bytes per stage (4 ksteps x 4KB)
#define SMEM_BYTES (W_OFF + 3 * WSTG)   // 116736

__device__ float g_ssum[E_EXP];
__device__ float g_cnt[E_EXP];
__device__ unsigned g_done;
// B tiles, ldmatrix layout: [ks][nt][pl][t][n-row] 16B rows  (1 MB)
__device__ __align__(16) uint32_t w_frag[NKS * 1024];

// exact 2-way fp16 split of (even,odd) f32 pair -> 2 packed f16x2 (lo=even)
__device__ __forceinline__ void split2v(float fe, float fo,
                                        uint32_t& h1, uint32_t& h2) {
    asm("cvt.rn.f16x2.f32 %0, %1, %2;" : "=r"(h1) : "f"(fo), "f"(fe));
    float ge, go;
    asm("{ .reg .f16 l, h; mov.b32 {l, h}, %2;"
        " cvt.f32.f16 %0, l; cvt.f32.f16 %1, h; }"
        : "=f"(ge), "=f"(go) : "r"(h1));
    asm("cvt.rn.f16x2.f32 %0, %1, %2;" : "=r"(h2) : "f"(fo - go), "f"(fe - ge));
}

#define MMA(acc, A, B)                                                        \
    asm volatile(                                                             \
        "mma.sync.aligned.m16n8k16.row.col.f32.f16.f16.f32 "                  \
        "{%0,%1,%2,%3}, {%4,%5,%6,%7}, {%8,%9}, {%0,%1,%2,%3};"               \
        : "+f"(acc[0]), "+f"(acc[1]), "+f"(acc[2]), "+f"(acc[3])              \
        : "r"(A[0]), "r"(A[1]), "r"(A[2]), "r"(A[3]), "r"(B.x), "r"(B.y))

#define LDMX4(r0, r1, r2, r3, a)                                              \
    asm volatile("ldmatrix.sync.aligned.m8n8.x4.shared.b16 {%0,%1,%2,%3}, [%4];" \
        : "=r"(r0), "=r"(r1), "=r"(r2), "=r"(r3) : "r"(a))

#define STS128(a, r0, r1, r2, r3)                                             \
    asm volatile("st.shared.v4.b32 [%0], {%1, %2, %3, %4};"                   \
        :: "r"(a), "r"(r0), "r"(r1), "r"(r2), "r"(r3) : "memory")

__device__ __forceinline__ void cp16(uint32_t sa, const void* g) {
    asm volatile("cp.async.cg.shared.global [%0], [%1], 16;" :: "r"(sa), "l"(g));
}
__device__ __forceinline__ uint32_t smem_u32(const void* p) {
    uint32_t a;
    asm("{ .reg .u64 t; cvta.to.shared.u64 t, %1; cvt.u32.u64 %0, t; }"
        : "=r"(a) : "l"(p));
    return a;
}

// Precompute w fp16x2 planes (scaled by 2^14) in ldmatrix tile layout.
__global__ void prep_w(const float* __restrict__ w) {
    if (blockIdx.x == 0) {
        if (threadIdx.x < E_EXP) {
            g_ssum[threadIdx.x] = 0.f;
            g_cnt[threadIdx.x] = 0.f;
        }
        if (threadIdx.x == 64) g_done = 0;
    }
    int i = blockIdx.x * blockDim.x + threadIdx.x;   // 32768 threads
    int t = i & 1, e = (i >> 1) & 63, ks = i >> 7;
    const float* src = w + (size_t)e * C_DIM + ks * 16 + t * 8;
    uint32_t h1[4], h2[4];
    #pragma unroll
    for (int p = 0; p < 4; p++)
        split2v(src[2 * p] * WSCALE, src[2 * p + 1] * WSCALE, h1[p], h2[p]);
    int nt = e >> 3, n = e & 7;
    char* base = (char*)w_frag + (size_t)ks * 4096 + nt * 512 + t * 128 + n * 16;
    *(uint4*)(base)       = make_uint4(h1[0], h1[1], h1[2], h1[3]);  // plane 1
    *(uint4*)(base + 256) = make_uint4(h2[0], h2[1], h2[2], h2[3]);  // plane 2
}

extern __shared__ __align__(16) char dsm[];

__global__ __launch_bounds__(NTH) void gate_kernel(
    const float* __restrict__ x, float* __restrict__ out)
{
    __shared__ int s_cnt[E_EXP];
    __shared__ int s_last;
    float* lg = (float*)dsm;                 // epilogue overlay [BT][65]

    const int tid = threadIdx.x, blk = blockIdx.x;
    const int wid = tid >> 5, lane = tid & 31;
    const int tg = wid & 7;                  // token group (16 tokens)
    const int nh = wid >> 3;                 // expert half (32 experts)
    const int qr = lane >> 2, qc = lane & 3;
    const uint32_t sb = smem_u32(dsm);

    // conversion geometry: thread -> (token t, kstep q within stage)
    const int ct = tid >> 2, cq = tid & 3;
    const int ctl = (ct >> 3) & 1;           // token half within 16-group
    const float* xg = x + (size_t)(blk * BT + ct) * C_DIM + cq * 16;
    const uint32_t st_base = (ct >> 4) * TG_STR + cq * KK_STR +
                             ctl * 128 + (ct & 7) * 16;

    // compute-side ldmatrix lane addresses
    const uint32_t lpart = ((lane >> 3) * 128) + ((lane & 7) * 16);
    const uint32_t pa_base = tg * TG_STR + lpart;          // + pbuf*P_STG + kk*KK_STR (+512 pl2)
    const uint32_t wlane  = (nh * 4) * 512 + lpart;        // + slot + kk*4096 + j*512

    if (tid < E_EXP) s_cnt[tid] = 0;

    float acc[4][4];
    #pragma unroll
    for (int j = 0; j < 4; j++)
        #pragma unroll
        for (int q = 0; q < 4; q++) acc[j][q] = 0.f;

    float4 xr[4];
    auto ldg_stage = [&](int st) {
        const float4* p = (const float4*)(xg + st * 64);
        xr[0] = p[0]; xr[1] = p[1]; xr[2] = p[2]; xr[3] = p[3];
    };
    auto emit_planes = [&](int pbuf) {
        uint32_t h1[8], h2[8];
        const float* f = (const float*)xr;
        #pragma unroll
        for (int j = 0; j < 8; j++)
            split2v(f[2 * j], f[2 * j + 1], h1[j], h2[j]);
        const uint32_t b = sb + pbuf * P_STG + st_base;
        STS128(b,             h1[0], h1[1], h1[2], h1[3]);  // pl1 klo
        STS128(b + 256,       h1[4], h1[5], h1[6], h1[7]);  // pl1 khi
        STS128(b + 512,       h2[0], h2[1], h2[2], h2[3]);  // pl2 klo
        STS128(b + 512 + 256, h2[4], h2[5], h2[6], h2[7]);  // pl2 khi
    };
    auto cpw = [&](int st, int slot) {
        const char* src = (const char*)w_frag + (size_t)st * WSTG + tid * 16;
        const uint32_t dst = sb + W_OFF + slot * WSTG + tid * 16;
        cp16(dst, src);
        cp16(dst + 8192, src + 8192);        // full 16KB stage
    };

    // prologue
    ldg_stage(0);
    cpw(0, 0); asm volatile("cp.async.commit_group;");
    cpw(1, 1); asm volatile("cp.async.commit_group;");
    emit_planes(0);                          // stage-0 planes, buffer 0
    ldg_stage(1);

    #pragma unroll 1
    for (int i = 0; i < NST; i++) {
        asm volatile("cp.async.wait_group 1;");   // stage-i w complete (this thread)
        __syncthreads();                          // all threads' copies + STS visible

        if (i + 2 < NST) cpw(i + 2, (i + 2) % 3);
        asm volatile("cp.async.commit_group;");

        // build planes for stage i+1 (xr holds its x); prefetch x for i+2
        if (i + 1 < NST) emit_planes((i + 1) & 1);
        if (i + 2 < NST) ldg_stage(i + 2);

        const uint32_t pA = sb + (i & 1) * P_STG + pa_base;
        const uint32_t wb = sb + W_OFF + (i % 3) * WSTG + wlane;

        #pragma unroll
        for (int kk = 0; kk < KPS; kk++) {
            uint32_t a1[4], a2[4];
            LDMX4(a1[0], a1[1], a1[2], a1[3], pA + kk * KK_STR);
            LDMX4(a2[0], a2[1], a2[2], a2[3], pA + kk * KK_STR + 512);
            uint2 b1[4], b2[4];
            #pragma unroll
            for (int j = 0; j < 4; j++) {
                uint32_t r0, r1, r2, r3;
                LDMX4(r0, r1, r2, r3, wb + kk * 4096 + j * 512);
                b1[j].x = r0; b1[j].y = r1;
                b2[j].x = r2; b2[j].y = r3;
            }
            #pragma unroll
            for (int j = 0; j < 4; j++) MMA(acc[j], a1, b1[j]);
            #pragma unroll
            for (int j = 0; j < 4; j++) MMA(acc[j], a2, b1[j]);
            #pragma unroll
            for (int j = 0; j < 4; j++) MMA(acc[j], a1, b2[j]);
        }
    }
    __syncthreads();    // staging done; reuse dsm as logits

    // scatter logits (descaled): row = tg*16 + qr (+8), col = (nh*4+j)*8 + 2*qc
    const int lr0 = tg * 16 + qr;
    #pragma unroll
    for (int j = 0; j < 4; j++) {
        const int e = (nh * 4 + j) * 8 + 2 * qc;
        lg[lr0 * 65 + e]           = acc[j][0] * WDESC;
        lg[lr0 * 65 + e + 1]       = acc[j][1] * WDESC;
        lg[(lr0 + 8) * 65 + e]     = acc[j][2] * WDESC;
        lg[(lr0 + 8) * 65 + e + 1] = acc[j][3] * WDESC;
    }
    __syncthreads();

    if (tid < BT) {
        float* row = lg + tid * 65;
        float v1 = -1e30f, v2 = -1e30f;
        int i1 = 0, i2 = 0;
        #pragma unroll
        for (int e = 0; e < E_EXP; e++) {
            float v = row[e];
            if (v > v1)      { v2 = v1; i2 = i1; v1 = v; i1 = e; }
            else if (v > v2) { v2 = v;  i2 = e; }
        }
        float Z = 0.f;
        #pragma unroll
        for (int e = 0; e < E_EXP; e++) {
            float ex = expf(row[e] - v1);
            row[e] = ex; Z += ex;
        }
        float rz = 1.0f / Z;
        #pragma unroll
        for (int e = 0; e < E_EXP; e++) row[e] *= rz;
        float s1 = row[i1], s2 = row[i2];
        float inv = 1.0f / (s1 + s2);
        int gt = blk * BT + tid;
        out[2 * gt]     = (float)i1;
        out[2 * gt + 1] = (float)i2;
        out[2 * T_TOKENS + 2 * gt]     = s1 * inv;
        out[2 * T_TOKENS + 2 * gt + 1] = s2 * inv;
        atomicAdd(&s_cnt[i1], 1);
        atomicAdd(&s_cnt[i2], 1);
    }
    __syncthreads();

    if (tid < E_EXP) {
        float sum = 0.f;
        for (int t = 0; t < BT; t++) sum += lg[t * 65 + tid];
        atomicAdd(&g_ssum[tid], sum);
        atomicAdd(&g_cnt[tid], (float)s_cnt[tid]);
    }
    __syncthreads();

    // last CTA computes aux loss
    if (tid == 0) {
        __threadfence();
        s_last = (atomicAdd(&g_done, 1u) == gridDim.x - 1);
    }
    __syncthreads();
    if (s_last) {
        if (tid < E_EXP) lg[tid] = g_ssum[tid] * g_cnt[tid];
        __syncthreads();
        if (tid == 0) {
            float s = 0.f;
            for (int e = 0; e < E_EXP; e++) s += lg[e];
            out[4 * T_TOKENS] = s * (ALPHA * (float)E_EXP /
                ((float)T_TOKENS * 2.0f * (float)T_TOKENS));
        }
    }
}

extern "C" void kernel_launch(void* const* d_in, const int* in_sizes, int n_in,
                              void* d_out, int out_size) {
    const float* x = (const float*)d_in[0];
    const float* w = (const float*)d_in[1];
    float* out = (float*)d_out;
    cudaFuncSetAttribute(gate_kernel,
                         cudaFuncAttributeMaxDynamicSharedMemorySize, SMEM_BYTES);
    prep_w<<<128, 256>>>(w);
    gate_kernel<<<T_TOKENS / BT, NTH, SMEM_BYTES>>>(x, out);
}

// round 16
// speedup vs baseline: 1.2467x; 1.1799x over previous
#include <cuda_runtime.h>
#include <math.h>
#include <stdint.h>

// SparseMoEGate via mma.sync (HMMA) fp16x2 exact-split GEMM (3 MMAs/k-step).
// R16 = R10 split into 2 CTAs/SM: BT=64, NTH=256 (8 warps), occupancy 2.
// Independent barrier domains interleave -> cross-CTA stall overlap; grid 256
// fills all SMs. Per-warp work identical to R10.
// x[16384,4096] f32, w[64,4096] f32
// out: [topk_idx as f32 (2T)] [topk_weight (2T)] [aux_loss (1)]

#define T_TOKENS 16384
#define C_DIM    4096
#define E_EXP    64
#define ALPHA    0.01f
#define WSCALE   16384.0f
#define WDESC    6.103515625e-05f   // 2^-14

#define BT    64              // tokens per CTA
#define NTH   256             // 8 warps
#define NKS   (C_DIM / 16)    // 256 k-steps
#define KPS   4               // k-steps per stage
#define NST   (NKS / KPS)     // 64 stages

#define XROW  272             // bytes per x row in smem (256B data + 16B pad)
#define XOFF_W 17408          // 64 * 272
#define WSTG  16384           // w bytes per stage (4 ksteps x 4KB)
#define SLOT  (XOFF_W + WSTG) // 33792
#define SMEM_BYTES (3 * SLOT) // 101376 per CTA (x2 CTAs = 198KB/SM)

__device__ float g_ssum[E_EXP];
__device__ float g_cnt[E_EXP];
__device__ unsigned g_done;
// B tiles, ldmatrix layout: [ks][nt][pl][t][n-row] 16B rows  (1 MB)
__device__ __align__(16) uint32_t w_frag[NKS * 1024];

// exact 2-way fp16 split of (even,odd) f32 pair -> 2 packed f16x2 (lo=even)
__device__ __forceinline__ void split2v(float fe, float fo,
                                        uint32_t& h1, uint32_t& h2) {
    asm("cvt.rn.f16x2.f32 %0, %1, %2;" : "=r"(h1) : "f"(fo), "f"(fe));
    float ge, go;
    asm("{ .reg .f16 l, h; mov.b32 {l, h}, %2;"
        " cvt.f32.f16 %0, l; cvt.f32.f16 %1, h; }"
        : "=f"(ge), "=f"(go) : "r"(h1));
    asm("cvt.rn.f16x2.f32 %0, %1, %2;" : "=r"(h2) : "f"(fo - go), "f"(fe - ge));
}

#define MMA(acc, A, B)                                                        \
    asm volatile(                                                             \
        "mma.sync.aligned.m16n8k16.row.col.f32.f16.f16.f32 "                  \
        "{%0,%1,%2,%3}, {%4,%5,%6,%7}, {%8,%9}, {%0,%1,%2,%3};"               \
        : "+f"(acc[0]), "+f"(acc[1]), "+f"(acc[2]), "+f"(acc[3])              \
        : "r"(A[0]), "r"(A[1]), "r"(A[2]), "r"(A[3]), "r"(B.x), "r"(B.y))

#define LDMX4(r0, r1, r2, r3, a)                                              \
    asm volatile("ldmatrix.sync.aligned.m8n8.x4.shared.b16 {%0,%1,%2,%3}, [%4];" \
        : "=r"(r0), "=r"(r1), "=r"(r2), "=r"(r3) : "r"(a))

__device__ __forceinline__ void cp16(uint32_t sa, const void* g) {
    asm volatile("cp.async.cg.shared.global [%0], [%1], 16;" :: "r"(sa), "l"(g));
}
__device__ __forceinline__ uint32_t smem_u32(const void* p) {
    uint32_t a;
    asm("{ .reg .u64 t; cvta.to.shared.u64 t, %1; cvt.u32.u64 %0, t; }"
        : "=r"(a) : "l"(p));
    return a;
}

// Precompute w fp16x2 planes (scaled by 2^14) in ldmatrix tile layout.
__global__ void prep_w(const float* __restrict__ w) {
    if (blockIdx.x == 0) {
        if (threadIdx.x < E_EXP) {
            g_ssum[threadIdx.x] = 0.f;
            g_cnt[threadIdx.x] = 0.f;
        }
        if (threadIdx.x == 64) g_done = 0;
    }
    int i = blockIdx.x * blockDim.x + threadIdx.x;   // 32768 threads
    int t = i & 1, e = (i >> 1) & 63, ks = i >> 7;
    const float* src = w + (size_t)e * C_DIM + ks * 16 + t * 8;
    uint32_t h1[4], h2[4];
    #pragma unroll
    for (int p = 0; p < 4; p++)
        split2v(src[2 * p] * WSCALE, src[2 * p + 1] * WSCALE, h1[p], h2[p]);
    int nt = e >> 3, n = e & 7;
    char* base = (char*)w_frag + (size_t)ks * 4096 + nt * 512 + t * 128 + n * 16;
    *(uint4*)(base)       = make_uint4(h1[0], h1[1], h1[2], h1[3]);  // plane 1
    *(uint4*)(base + 256) = make_uint4(h2[0], h2[1], h2[2], h2[3]);  // plane 2
}

extern __shared__ __align__(16) char dsm[];

__global__ __launch_bounds__(NTH, 2) void gate_kernel(
    const float* __restrict__ x, float* __restrict__ out)
{
    __shared__ int s_cnt[E_EXP];
    __shared__ int s_last;
    float* lg = (float*)dsm;                 // epilogue overlay [BT][65]

    const int tid = threadIdx.x, blk = blockIdx.x;
    const int wid = tid >> 5, lane = tid & 31;
    const int tg = wid & 3;                  // token group (16 tokens)
    const int nh = wid >> 2;                 // expert half (32 experts)
    const int qr = lane >> 2, qc = lane & 3;
    const uint32_t sb = smem_u32(dsm);

    const int xr_lo = tg * 16 + qr;          // rows 0..63
    const int xr_hi = xr_lo + 8;
    const uint32_t lpart = ((lane >> 3) * 128) + ((lane & 7) * 16);
    const uint32_t wlane = (nh * 4) * 512 + lpart;

    // cp geometry: 256 thr -> 32 rows x 8 segs(16B), 2 row-halves
    const int crow = tid >> 3, cseg = tid & 7;
    const float* xg = x + (size_t)(blk * BT + crow) * C_DIM + cseg * 4;

    if (tid < E_EXP) s_cnt[tid] = 0;

    float acc[4][4];
    #pragma unroll
    for (int j = 0; j < 4; j++)
        #pragma unroll
        for (int q = 0; q < 4; q++) acc[j][q] = 0.f;

    auto stage_cp = [&](int st, int slot) {
        const uint32_t base = sb + slot * SLOT;
        // x: 64 rows x 256B (272B pitch), coalesced
        #pragma unroll
        for (int rh = 0; rh < 2; rh++)
            #pragma unroll
            for (int kh = 0; kh < 2; kh++)
                cp16(base + (crow + rh * 32) * XROW + kh * 128 + cseg * 16,
                     xg + (size_t)(rh * 32) * C_DIM + st * 64 + kh * 32);
        // w tiles: 16KB (256 thr x 4 x 16B)
        const char* wsrc = (const char*)w_frag + (size_t)st * WSTG + tid * 16;
        const uint32_t wdst = base + XOFF_W + tid * 16;
        #pragma unroll
        for (int o = 0; o < 4; o++)
            cp16(wdst + o * 4096, wsrc + o * 4096);
    };

    stage_cp(0, 0); asm volatile("cp.async.commit_group;");
    stage_cp(1, 1); asm volatile("cp.async.commit_group;");

    #pragma unroll 1
    for (int i = 0; i < NST; i++) {
        asm volatile("cp.async.wait_group 1;");
        __syncthreads();                     // stage i visible; slot (i+2)%3 free

        if (i + 2 < NST) stage_cp(i + 2, (i + 2) % 3);
        asm volatile("cp.async.commit_group;");

        const char* xs = dsm + (i % 3) * SLOT;
        const uint32_t wb = sb + (i % 3) * SLOT + XOFF_W + wlane;

        #pragma unroll
        for (int kk = 0; kk < KPS; kk++) {
            float2 x0 = *(const float2*)(xs + xr_lo * XROW + kk * 64 + qc * 8);
            float2 x1 = *(const float2*)(xs + xr_hi * XROW + kk * 64 + qc * 8);
            float2 x2 = *(const float2*)(xs + xr_lo * XROW + kk * 64 + 32 + qc * 8);
            float2 x3 = *(const float2*)(xs + xr_hi * XROW + kk * 64 + 32 + qc * 8);

            // A frag order [r0/klo, r1/klo, r0/khi, r1/khi]
            uint32_t a1[4], a2[4];
            split2v(x0.x, x0.y, a1[0], a2[0]);
            split2v(x1.x, x1.y, a1[1], a2[1]);
            split2v(x2.x, x2.y, a1[2], a2[2]);
            split2v(x3.x, x3.y, a1[3], a2[3]);

            uint2 b1[4], b2[4];
            #pragma unroll
            for (int j = 0; j < 4; j++) {
                uint32_t r0, r1, r2, r3;
                LDMX4(r0, r1, r2, r3, wb + kk * 4096 + j * 512);
                b1[j].x = r0; b1[j].y = r1;
                b2[j].x = r2; b2[j].y = r3;
            }
            #pragma unroll
            for (int j = 0; j < 4; j++) MMA(acc[j], a1, b1[j]);
            #pragma unroll
            for (int j = 0; j < 4; j++) MMA(acc[j], a2, b1[j]);
            #pragma unroll
            for (int j = 0; j < 4; j++) MMA(acc[j], a1, b2[j]);
        }
    }
    __syncthreads();    // staging done; reuse dsm as logits

    // scatter logits (descaled): row = tg*16 + qr (+8), col = (nh*4+j)*8 + 2*qc
    const int lr0 = tg * 16 + qr;
    #pragma unroll
    for (int j = 0; j < 4; j++) {
        const int e = (nh * 4 + j) * 8 + 2 * qc;
        lg[lr0 * 65 + e]           = acc[j][0] * WDESC;
        lg[lr0 * 65 + e + 1]       = acc[j][1] * WDESC;
        lg[(lr0 + 8) * 65 + e]     = acc[j][2] * WDESC;
        lg[(lr0 + 8) * 65 + e + 1] = acc[j][3] * WDESC;
    }
    __syncthreads();

    if (tid < BT) {
        float* row = lg + tid * 65;
        float v1 = -1e30f, v2 = -1e30f;
        int i1 = 0, i2 = 0;
        #pragma unroll
        for (int e = 0; e < E_EXP; e++) {
            float v = row[e];
            if (v > v1)      { v2 = v1; i2 = i1; v1 = v; i1 = e; }
            else if (v > v2) { v2 = v;  i2 = e; }
        }
        float Z = 0.f;
        #pragma unroll
        for (int e = 0; e < E_EXP; e++) {
            float ex = expf(row[e] - v1);
            row[e] = ex; Z += ex;
        }
        float rz = 1.0f / Z;
        #pragma unroll
        for (int e = 0; e < E_EXP; e++) row[e] *= rz;
        float s1 = row[i1], s2 = row[i2];
        float inv = 1.0f / (s1 + s2);
        int gt = blk * BT + tid;
        out[2 * gt]     = (float)i1;
        out[2 * gt + 1] = (float)i2;
        out[2 * T_TOKENS + 2 * gt]     = s1 * inv;
        out[2 * T_TOKENS + 2 * gt + 1] = s2 * inv;
        atomicAdd(&s_cnt[i1], 1);
        atomicAdd(&s_cnt[i2], 1);
    }
    __syncthreads();

    if (tid < E_EXP) {
        float sum = 0.f;
        for (int t = 0; t < BT; t++) sum += lg[t * 65 + tid];
        atomicAdd(&g_ssum[tid], sum);
        atomicAdd(&g_cnt[tid], (float)s_cnt[tid]);
    }
    __syncthreads();

    // last CTA computes aux loss
    if (tid == 0) {
        __threadfence();
        s_last = (atomicAdd(&g_done, 1u) == gridDim.x - 1);
    }
    __syncthreads();
    if (s_last) {
        if (tid < E_EXP) lg[tid] = g_ssum[tid] * g_cnt[tid];
        __syncthreads();
        if (tid == 0) {
            float s = 0.f;
            for (int e = 0; e < E_EXP; e++) s += lg[e];
            out[4 * T_TOKENS] = s * (ALPHA * (float)E_EXP /
                ((float)T_TOKENS * 2.0f * (float)T_TOKENS));
        }
    }
}

extern "C" void kernel_launch(void* const* d_in, const int* in_sizes, int n_in,
                              void* d_out, int out_size) {
    const float* x = (const float*)d_in[0];
    const float* w = (const float*)d_in[1];
    float* out = (float*)d_out;
    cudaFuncSetAttribute(gate_kernel,
                         cudaFuncAttributeMaxDynamicSharedMemorySize, SMEM_BYTES);
    prep_w<<<128, 256>>>(w);
    gate_kernel<<<T_TOKENS / BT, NTH, SMEM_BYTES>>>(x, out);
}